// round 11
// baseline (speedup 1.0000x reference)
#include <cuda_runtime.h>
#include <cstdint>
#include <math.h>

// Pacemaker: OU process + Bernoulli spikes, bit-matching JAX threefry2x32
// (partitionable) + XLA erfinv. T=16384, N=8192, out f32 [T,N].
//
// R10: one co-resident kernel. Roles by bid (monotonic dispatch):
//   [0,32)            : scan blocks (256 thr, thread=neuron), counter-gated
//                       prefetch depth 2, release g_scnt[c] per chunk
//   [32, 32+131072)   : noise tiles, chunk-major; release g_ncnt[c]
//   [.., +131072)     : spike tiles, chunk-major; wait g_scnt[c]==32
// Scan (memory-bound, <2% issue) hides fully under noise (alu-bound).

#define T_STEPS 16384
#define N_NEUR  8192
#define NCHUNK  512                     // T/32
#define SCANB   32                      // N/256
#define TILES_PER_CHUNK 256             // (32t x 8192i) / 1024 elems per block
#define NOISE_BLOCKS (NCHUNK * TILES_PER_CHUNK)

__device__ uint2 g_kn[T_STEPS];
__device__ uint2 g_kb[T_STEPS];
__device__ __align__(16) float g_noise[(size_t)T_STEPS * N_NEUR];
__device__ int g_ncnt[NCHUNK];
__device__ int g_scnt[NCHUNK];

// ---------------------------------------------------------------------------
// sync helpers (fixed short sleep — R8's exponential backoff was the bug)
// ---------------------------------------------------------------------------
__device__ __forceinline__ int ld_acq(const int* p) {
  int v;
  asm volatile("ld.acquire.gpu.global.b32 %0, [%1];" : "=r"(v) : "l"(p) : "memory");
  return v;
}
__device__ __forceinline__ void red_rel(int* p) {
  asm volatile("red.release.gpu.global.add.s32 [%0], %1;" :: "l"(p), "r"(1) : "memory");
}
__device__ __forceinline__ void wait_cnt(const int* p, int target) {
  while (ld_acq(p) < target) __nanosleep(128);
}

// ---------------------------------------------------------------------------
// threefry2x32 (20 rounds) — identical to jax._src.prng.threefry2x32
// (plain adds: R9 showed IMAD adds +1cyc/hop on the serial chain)
// ---------------------------------------------------------------------------
__device__ __forceinline__ void tf_round4(uint32_t& x0, uint32_t& x1,
                                          int r0, int r1, int r2, int r3) {
  x0 += x1; x1 = __funnelshift_l(x1, x1, r0); x1 ^= x0;
  x0 += x1; x1 = __funnelshift_l(x1, x1, r1); x1 ^= x0;
  x0 += x1; x1 = __funnelshift_l(x1, x1, r2); x1 ^= x0;
  x0 += x1; x1 = __funnelshift_l(x1, x1, r3); x1 ^= x0;
}
__device__ __forceinline__ uint2 threefry2x32(uint32_t k0, uint32_t k1,
                                              uint32_t x0, uint32_t x1) {
  uint32_t ks2 = k0 ^ k1 ^ 0x1BD11BDAu;
  x0 += k0; x1 += k1;
  tf_round4(x0, x1, 13, 15, 26, 6);  x0 += k1;  x1 += ks2 + 1u;
  tf_round4(x0, x1, 17, 29, 16, 24); x0 += ks2; x1 += k0  + 2u;
  tf_round4(x0, x1, 13, 15, 26, 6);  x0 += k0;  x1 += k1  + 3u;
  tf_round4(x0, x1, 17, 29, 16, 24); x0 += k1;  x1 += ks2 + 4u;
  tf_round4(x0, x1, 13, 15, 26, 6);  x0 += ks2; x1 += k0  + 5u;
  return make_uint2(x0, x1);
}

// uniform [0,1): bitcast((bits>>9)|0x3f800000) - 1  (exact, matches jax)
__device__ __forceinline__ float u01_from_bits(uint32_t bits) {
  return __fsub_rn(__uint_as_float((bits >> 9) | 0x3f800000u), 1.0f);
}

// XLA ErfInv (f32, Giles). Separate mul/add (XLA does not form FMAs).
__device__ __forceinline__ float erfinv_xla(float x) {
  float w = -log1pf(-__fmul_rn(x, x));
  float p;
  if (w < 5.0f) {
    w = __fadd_rn(w, -2.5f);
    p = 2.81022636e-08f;
    p = __fadd_rn(3.43273939e-07f,  __fmul_rn(p, w));
    p = __fadd_rn(-3.5233877e-06f,  __fmul_rn(p, w));
    p = __fadd_rn(-4.39150654e-06f, __fmul_rn(p, w));
    p = __fadd_rn(0.00021858087f,   __fmul_rn(p, w));
    p = __fadd_rn(-0.00125372503f,  __fmul_rn(p, w));
    p = __fadd_rn(-0.00417768164f,  __fmul_rn(p, w));
    p = __fadd_rn(0.246640727f,     __fmul_rn(p, w));
    p = __fadd_rn(1.50140941f,      __fmul_rn(p, w));
  } else {
    w = __fadd_rn(__fsqrt_rn(w), -3.0f);
    p = -0.000200214257f;
    p = __fadd_rn(0.000100950558f,  __fmul_rn(p, w));
    p = __fadd_rn(0.00134934322f,   __fmul_rn(p, w));
    p = __fadd_rn(-0.00367342844f,  __fmul_rn(p, w));
    p = __fadd_rn(0.00573950773f,   __fmul_rn(p, w));
    p = __fadd_rn(-0.0076224613f,   __fmul_rn(p, w));
    p = __fadd_rn(0.00943887047f,   __fmul_rn(p, w));
    p = __fadd_rn(1.00167406f,      __fmul_rn(p, w));
    p = __fadd_rn(2.83297682f,      __fmul_rn(p, w));
  }
  return __fmul_rn(p, x);
}

// ---------------------------------------------------------------------------
// K0: per-step keys + counter reset (same stream, precedes k_pipe).
// ---------------------------------------------------------------------------
__global__ void __launch_bounds__(256) k_keys() {
  int t = blockIdx.x * blockDim.x + threadIdx.x;
  if (t < NCHUNK) { g_ncnt[t] = 0; g_scnt[t] = 0; }
  if (t >= T_STEPS) return;
  uint2 kt = threefry2x32(0u, 0u, 0u, (uint32_t)t);
  g_kn[t] = threefry2x32(kt.x, kt.y, 0u, 0u);
  g_kb[t] = threefry2x32(kt.x, kt.y, 0u, 1u);
}

// ---------------------------------------------------------------------------
// K1: pipelined mega-kernel
// ---------------------------------------------------------------------------
__global__ void __launch_bounds__(256) k_pipe(const float* __restrict__ state,
                                              float* __restrict__ out) {
  const unsigned bid = blockIdx.x;
  const int tid = threadIdx.x;

  if (bid < SCANB) {
    // ================= scan role: thread = neuron =================
    const int i = (int)bid * 256 + tid;
    float x = state[i];
    const float DT_F = 0.001f;
    const float* __restrict__ src = g_noise + i;

    float b0[32], b1[32];
    wait_cnt(&g_ncnt[0], TILES_PER_CHUNK);
#pragma unroll
    for (int k = 0; k < 32; k++) b0[k] = __ldcg(src + (size_t)k * N_NEUR);
    wait_cnt(&g_ncnt[1], TILES_PER_CHUNK);
#pragma unroll
    for (int k = 0; k < 32; k++) b1[k] = __ldcg(src + (size_t)(32 + k) * N_NEUR);

    for (int c = 0; c < NCHUNK; c++) {
      float pf[32];
      int pc = c + 2;
      if (pc < NCHUNK) {
        wait_cnt(&g_ncnt[pc], TILES_PER_CHUNK);
        const float* ps = src + (size_t)pc * 32 * N_NEUR;
#pragma unroll
        for (int k = 0; k < 32; k++) pf[k] = __ldcg(ps + (size_t)k * N_NEUR);
      }

      float* dst = out + (size_t)c * 32 * N_NEUR + i;
#pragma unroll
      for (int k = 0; k < 32; k++) {
        x = __fadd_rn(__fsub_rn(x, __fmul_rn(x, DT_F)), b0[k]);
        dst[(size_t)k * N_NEUR] = x;
      }
      __threadfence();
      __syncthreads();
      if (tid == 0) red_rel(&g_scnt[c]);

#pragma unroll
      for (int k = 0; k < 32; k++) { b0[k] = b1[k]; b1[k] = pf[k]; }
    }
    return;
  }

  if (bid < SCANB + NOISE_BLOCKS) {
    // ================= noise role: chunk-major tiles =================
    const unsigned nb = bid - SCANB;
    const int chunk = (int)(nb >> 8);
    const int tile  = (int)(nb & 255);              // 4 t-groups x 64 i-groups
    const int t  = chunk * 32 + (tile >> 6) * 8 + (tid >> 5);
    const int i0 = (tile & 63) * 128 + (tid & 31) * 4;

    uint2 kn = g_kn[t];                             // warp-uniform

    const float LO  = __uint_as_float(0xBF7FFFFFu); // nextafter(-1, 0)
    const float SQ2 = __uint_as_float(0x3FB504F3u); // float(sqrt(2))
    const float NS  = (float)(0.6 * sqrt(0.001));   // sigma * sqrt(dt)

    float tmp[4];
#pragma unroll
    for (int j = 0; j < 4; j++) {
      uint2 r = threefry2x32(kn.x, kn.y, 0u, (uint32_t)(i0 + j));
      float f = u01_from_bits(r.x ^ r.y);
      float u = __fadd_rn(__fmul_rn(f, 2.0f), LO);
      u = fmaxf(LO, u);
      tmp[j] = __fmul_rn(__fmul_rn(SQ2, erfinv_xla(u)), NS);
    }
    float4 o; o.x = tmp[0]; o.y = tmp[1]; o.z = tmp[2]; o.w = tmp[3];
    *reinterpret_cast<float4*>(g_noise + (size_t)t * N_NEUR + i0) = o;

    __threadfence();
    __syncthreads();
    if (tid == 0) red_rel(&g_ncnt[chunk]);
    return;
  }

  // ================= spike role: chunk-major tiles =================
  {
    const unsigned sb = bid - SCANB - NOISE_BLOCKS;
    const int chunk = (int)(sb >> 8);
    const int tile  = (int)(sb & 255);              // 32 t x 8 i-groups
    const int t  = chunk * 32 + (tile >> 3);
    const int i0 = (tile & 7) * 1024 + tid * 4;

    wait_cnt(&g_scnt[chunk], 256 * SCANB / 256);    // == 32

    uint2 kb = g_kb[t];                             // block-uniform
    const size_t base = (size_t)t * N_NEUR + i0;
    float4 xv = __ldcg(reinterpret_cast<const float4*>(out + base));
    const float RDT = 0.003f;                       // rate * dt
    float xs[4] = {xv.x, xv.y, xv.z, xv.w};
    float sv[4];
#pragma unroll
    for (int j = 0; j < 4; j++) {
      uint2 r  = threefry2x32(kb.x, kb.y, 0u, (uint32_t)(i0 + j));
      float u  = u01_from_bits(r.x ^ r.y);
      float pr = __fadd_rn(RDT, xs[j]);
      pr = fminf(fmaxf(pr, 0.0f), 1.0f);            // jnp.clip
      sv[j] = (u < pr) ? 1.0f : 0.0f;
    }
    float4 s; s.x = sv[0]; s.y = sv[1]; s.z = sv[2]; s.w = sv[3];
    *reinterpret_cast<float4*>(out + base) = s;
  }
}

// ---------------------------------------------------------------------------
// launch
// ---------------------------------------------------------------------------
extern "C" void kernel_launch(void* const* d_in, const int* in_sizes, int n_in,
                              void* d_out, int out_size) {
  const float* state = (const float*)d_in[0];   // zeros [N]
  float* out = (float*)d_out;                   // f32 [T*N]

  k_keys<<<T_STEPS / 256, 256>>>();
  k_pipe<<<SCANB + NOISE_BLOCKS + NOISE_BLOCKS, 256>>>(state, out);
}

// round 12
// speedup vs baseline: 1.5113x; 1.5113x over previous
#include <cuda_runtime.h>
#include <cstdint>
#include <math.h>

// Pacemaker: OU process + Bernoulli spikes, bit-matching JAX threefry2x32
// (partitionable) + XLA erfinv. T=16384, N=8192, out f32 [T,N].
//
// R11 = R7 skeleton with two component rewrites:
//  k_scan : helper-warp smem staging (1 compute + 7 loader warps per block,
//           named-barrier handshake) -> breaks the per-warp MLP cap (~55
//           outstanding LDG) that kept 485us; loaders also do the x stores.
//  k_spike: 32t x 32i tile, smem transpose, warp = 4 neurons x 32t rows,
//           per-row ballot skips the Bernoulli threefry for fully-decided
//           rows (~45%, OU time-correlation).

#define T_STEPS 16384
#define N_NEUR  8192
#define NCHUNK  512          // T/32

__device__ uint2 g_kn[T_STEPS];
__device__ uint2 g_kb[T_STEPS];
// noise, T-MAJOR: g_noise[t * N_NEUR + i]
__device__ __align__(16) float g_noise[(size_t)T_STEPS * N_NEUR];

// ---------------------------------------------------------------------------
// threefry2x32 (20 rounds) — identical to jax._src.prng.threefry2x32
// ---------------------------------------------------------------------------
__device__ __forceinline__ void tf_round4(uint32_t& x0, uint32_t& x1,
                                          int r0, int r1, int r2, int r3) {
  x0 += x1; x1 = __funnelshift_l(x1, x1, r0); x1 ^= x0;
  x0 += x1; x1 = __funnelshift_l(x1, x1, r1); x1 ^= x0;
  x0 += x1; x1 = __funnelshift_l(x1, x1, r2); x1 ^= x0;
  x0 += x1; x1 = __funnelshift_l(x1, x1, r3); x1 ^= x0;
}
__device__ __forceinline__ uint2 threefry2x32(uint32_t k0, uint32_t k1,
                                              uint32_t x0, uint32_t x1) {
  uint32_t ks2 = k0 ^ k1 ^ 0x1BD11BDAu;
  x0 += k0; x1 += k1;
  tf_round4(x0, x1, 13, 15, 26, 6);  x0 += k1;  x1 += ks2 + 1u;
  tf_round4(x0, x1, 17, 29, 16, 24); x0 += ks2; x1 += k0  + 2u;
  tf_round4(x0, x1, 13, 15, 26, 6);  x0 += k0;  x1 += k1  + 3u;
  tf_round4(x0, x1, 17, 29, 16, 24); x0 += k1;  x1 += ks2 + 4u;
  tf_round4(x0, x1, 13, 15, 26, 6);  x0 += ks2; x1 += k0  + 5u;
  return make_uint2(x0, x1);
}

// uniform [0,1): bitcast((bits>>9)|0x3f800000) - 1  (exact, matches jax)
__device__ __forceinline__ float u01_from_bits(uint32_t bits) {
  return __fsub_rn(__uint_as_float((bits >> 9) | 0x3f800000u), 1.0f);
}

// XLA ErfInv (f32, Giles). Separate mul/add (XLA does not form FMAs).
__device__ __forceinline__ float erfinv_xla(float x) {
  float w = -log1pf(-__fmul_rn(x, x));
  float p;
  if (w < 5.0f) {
    w = __fadd_rn(w, -2.5f);
    p = 2.81022636e-08f;
    p = __fadd_rn(3.43273939e-07f,  __fmul_rn(p, w));
    p = __fadd_rn(-3.5233877e-06f,  __fmul_rn(p, w));
    p = __fadd_rn(-4.39150654e-06f, __fmul_rn(p, w));
    p = __fadd_rn(0.00021858087f,   __fmul_rn(p, w));
    p = __fadd_rn(-0.00125372503f,  __fmul_rn(p, w));
    p = __fadd_rn(-0.00417768164f,  __fmul_rn(p, w));
    p = __fadd_rn(0.246640727f,     __fmul_rn(p, w));
    p = __fadd_rn(1.50140941f,      __fmul_rn(p, w));
  } else {
    w = __fadd_rn(__fsqrt_rn(w), -3.0f);
    p = -0.000200214257f;
    p = __fadd_rn(0.000100950558f,  __fmul_rn(p, w));
    p = __fadd_rn(0.00134934322f,   __fmul_rn(p, w));
    p = __fadd_rn(-0.00367342844f,  __fmul_rn(p, w));
    p = __fadd_rn(0.00573950773f,   __fmul_rn(p, w));
    p = __fadd_rn(-0.0076224613f,   __fmul_rn(p, w));
    p = __fadd_rn(0.00943887047f,   __fmul_rn(p, w));
    p = __fadd_rn(1.00167406f,      __fmul_rn(p, w));
    p = __fadd_rn(2.83297682f,      __fmul_rn(p, w));
  }
  return __fmul_rn(p, x);
}

// ---------------------------------------------------------------------------
// K0: per-step keys.
// ---------------------------------------------------------------------------
__global__ void __launch_bounds__(256) k_keys() {
  int t = blockIdx.x * blockDim.x + threadIdx.x;
  if (t >= T_STEPS) return;
  uint2 kt = threefry2x32(0u, 0u, 0u, (uint32_t)t);
  g_kn[t] = threefry2x32(kt.x, kt.y, 0u, 0u);
  g_kb[t] = threefry2x32(kt.x, kt.y, 0u, 1u);
}

// ---------------------------------------------------------------------------
// K1: noise gen, T-MAJOR (unchanged from R7: alu-bound at its floor).
// ---------------------------------------------------------------------------
__global__ void __launch_bounds__(256) k_noise() {
  const int IB = N_NEUR / 128;
  const unsigned b = blockIdx.x;
  const int ib = (int)(b % IB);
  const int tb = (int)(b / IB);
  const int t  = tb * 8 + (threadIdx.x >> 5);
  const int i0 = ib * 128 + (threadIdx.x & 31) * 4;

  uint2 kn = g_kn[t];                               // warp-uniform

  const float LO  = __uint_as_float(0xBF7FFFFFu);   // nextafter(-1, 0)
  const float SQ2 = __uint_as_float(0x3FB504F3u);   // float(sqrt(2))
  const float NS  = (float)(0.6 * sqrt(0.001));     // sigma * sqrt(dt)

  float tmp[4];
#pragma unroll
  for (int j = 0; j < 4; j++) {
    uint2 r = threefry2x32(kn.x, kn.y, 0u, (uint32_t)(i0 + j));
    float f = u01_from_bits(r.x ^ r.y);
    float u = __fadd_rn(__fmul_rn(f, 2.0f), LO);
    u = fmaxf(LO, u);
    tmp[j] = __fmul_rn(__fmul_rn(SQ2, erfinv_xla(u)), NS);
  }
  float4 o; o.x = tmp[0]; o.y = tmp[1]; o.z = tmp[2]; o.w = tmp[3];
  *reinterpret_cast<float4*>(g_noise + (size_t)t * N_NEUR + i0) = o;
}

// ---------------------------------------------------------------------------
// K2: scan with helper warps. Block = 256 thr: warp0 = compute (32 neurons,
// exact FP chain); warps 1..7 = loaders, each owning one smem slot and every
// 7th chunk. Handshake: bar.sync(w, 64) pairs {warp0, warp w}: loader fills
// slot -> barR -> barC -> stores x tile to out -> fills next. Compute:
// barR -> chain in-place in smem -> barC. Counts match exactly (2 per chunk
// on each side). Loaders give ~7MB chip-wide in-flight loads and take the
// t-major x stores off the serial-chain warp.
// ---------------------------------------------------------------------------
__global__ void __launch_bounds__(256) k_scan(const float* __restrict__ state,
                                              float* __restrict__ out) {
  __shared__ float tile[7][32][33];   // slot x t x i(+pad)
  const int w    = threadIdx.x >> 5;
  const int lane = threadIdx.x & 31;
  const int i0   = blockIdx.x * 32;

  if (w == 0) {
    // ---------------- compute warp ----------------
    float x = state[i0 + lane];
    const float DT_F = 0.001f;
    for (int c = 0; c < NCHUNK; c++) {
      const int lw = 1 + (c % 7);
      float* col = &tile[c % 7][0][lane];
      asm volatile("bar.sync %0, 64;" :: "r"(lw) : "memory");   // ready
#pragma unroll
      for (int k = 0; k < 32; k++) {
        float n = col[k * 33];
        x = __fadd_rn(__fsub_rn(x, __fmul_rn(x, DT_F)), n);
        col[k * 33] = x;
      }
      asm volatile("bar.sync %0, 64;" :: "r"(lw) : "memory");   // consumed
    }
  } else {
    // ---------------- loader warp w ----------------
    const int slot = w - 1;
    for (int c = w - 1; c < NCHUNK; c += 7) {
      const float* src = g_noise + (size_t)c * 32 * N_NEUR + i0 + lane;
#pragma unroll
      for (int k = 0; k < 32; k++)
        tile[slot][k][lane] = __ldcs(src + (size_t)k * N_NEUR);
      asm volatile("bar.sync %0, 64;" :: "r"(w) : "memory");    // ready
      asm volatile("bar.sync %0, 64;" :: "r"(w) : "memory");    // consumed
      float* dst = out + (size_t)c * 32 * N_NEUR + i0 + lane;
#pragma unroll
      for (int k = 0; k < 32; k++)
        dst[(size_t)k * N_NEUR] = tile[slot][k][lane];
    }
  }
}

// ---------------------------------------------------------------------------
// K3: spikes with per-neuron-row coherent skip. Block = 32t x 32i tile.
// P1: float4 t-major loads -> smem (scalar STS, pitch 33).
// P2: warp = 4 neuron columns x 32t (lane = t). Per column: ballot on
//     decided = (p<=0 | p>=1); if whole row decided -> skip threefry.
// P3: smem -> float4 t-major stores (in place on d_out).
// ---------------------------------------------------------------------------
__global__ void __launch_bounds__(256) k_spike(float* __restrict__ out) {
  __shared__ float xs[32][33];
  __shared__ float sp[32][33];

  const unsigned b = blockIdx.x;
  const int i0 = (int)(b & 255) * 32;
  const int t0 = (int)(b >> 8) * 32;
  const int tid = threadIdx.x;
  const int tl = tid >> 3;            // 0..31 (t row)
  const int il = (tid & 7) * 4;       // 0..28 (i within tile)

  // P1: load x tile
  float4 v = *reinterpret_cast<const float4*>(out + (size_t)(t0 + tl) * N_NEUR + i0 + il);
  xs[tl][il]     = v.x;
  xs[tl][il + 1] = v.y;
  xs[tl][il + 2] = v.z;
  xs[tl][il + 3] = v.w;
  __syncthreads();

  // P2: per-neuron-row spike with coherent skip
  const int w    = tid >> 5;
  const int lane = tid & 31;
  const float RDT = 0.003f;           // rate * dt
  uint2 kb = g_kb[t0 + lane];         // per-lane (per-t) key

#pragma unroll
  for (int r = 0; r < 4; r++) {
    const int ic = w * 4 + r;         // neuron column in tile
    float x  = xs[lane][ic];
    float pr = __fadd_rn(RDT, x);
    bool dec = (pr <= 0.0f) | (pr >= 1.0f);
    unsigned ball = __ballot_sync(0xffffffffu, dec);
    float s;
    if (ball == 0xffffffffu) {
      s = (pr >= 1.0f) ? 1.0f : 0.0f; // u in [0,1): p<=0 never, p>=1 always
    } else {
      uint2 rr = threefry2x32(kb.x, kb.y, 0u, (uint32_t)(i0 + ic));
      float u  = u01_from_bits(rr.x ^ rr.y);
      float pc = fminf(fmaxf(pr, 0.0f), 1.0f);   // jnp.clip
      s = (u < pc) ? 1.0f : 0.0f;
    }
    sp[lane][ic] = s;
  }
  __syncthreads();

  // P3: store spike tile
  float4 o;
  o.x = sp[tl][il];
  o.y = sp[tl][il + 1];
  o.z = sp[tl][il + 2];
  o.w = sp[tl][il + 3];
  *reinterpret_cast<float4*>(out + (size_t)(t0 + tl) * N_NEUR + i0 + il) = o;
}

// ---------------------------------------------------------------------------
// launch
// ---------------------------------------------------------------------------
extern "C" void kernel_launch(void* const* d_in, const int* in_sizes, int n_in,
                              void* d_out, int out_size) {
  const float* state = (const float*)d_in[0];   // zeros [N]
  float* out = (float*)d_out;                   // f32 [T*N]

  k_keys <<<T_STEPS / 256, 256>>>();
  k_noise<<<(N_NEUR / 128) * (T_STEPS / 8), 256>>>();
  k_scan <<<N_NEUR / 32, 256>>>(state, out);
  k_spike<<<NCHUNK * (N_NEUR / 32), 256>>>(out);
}

// round 13
// speedup vs baseline: 1.7872x; 1.1825x over previous
#include <cuda_runtime.h>
#include <cstdint>
#include <math.h>

// Pacemaker: OU process + Bernoulli spikes, bit-matching JAX threefry2x32
// (partitionable) + XLA erfinv. T=16384, N=8192, out f32 [T,N].
//
// R12 = R11 with k_spike fused into k_scan's loader warps:
//   block = 384 thr: warp0 = compute (32 neurons, FP-exact chain in smem),
//   warps 1..11 = loaders, each owning one smem slot and every 11th chunk.
//   loader: fill noise tile -> barR -> [compute rewrites tile with x] -> barC
//           -> spike compute on tile (lane=t, 32 neuron cols, ballot skip)
//           -> store SPIKES t-major to d_out.
//   Kills the 512MB x-write + 512MB x-read between scan and spike.

#define T_STEPS 16384
#define N_NEUR  8192
#define NCHUNK  512          // T/32
#define NLOAD   11           // loader warps / smem slots per block

__device__ uint2 g_kn[T_STEPS];
__device__ uint2 g_kb[T_STEPS];
// noise, T-MAJOR: g_noise[t * N_NEUR + i]
__device__ __align__(16) float g_noise[(size_t)T_STEPS * N_NEUR];

// ---------------------------------------------------------------------------
// threefry2x32 (20 rounds) — identical to jax._src.prng.threefry2x32
// ---------------------------------------------------------------------------
__device__ __forceinline__ void tf_round4(uint32_t& x0, uint32_t& x1,
                                          int r0, int r1, int r2, int r3) {
  x0 += x1; x1 = __funnelshift_l(x1, x1, r0); x1 ^= x0;
  x0 += x1; x1 = __funnelshift_l(x1, x1, r1); x1 ^= x0;
  x0 += x1; x1 = __funnelshift_l(x1, x1, r2); x1 ^= x0;
  x0 += x1; x1 = __funnelshift_l(x1, x1, r3); x1 ^= x0;
}
__device__ __forceinline__ uint2 threefry2x32(uint32_t k0, uint32_t k1,
                                              uint32_t x0, uint32_t x1) {
  uint32_t ks2 = k0 ^ k1 ^ 0x1BD11BDAu;
  x0 += k0; x1 += k1;
  tf_round4(x0, x1, 13, 15, 26, 6);  x0 += k1;  x1 += ks2 + 1u;
  tf_round4(x0, x1, 17, 29, 16, 24); x0 += ks2; x1 += k0  + 2u;
  tf_round4(x0, x1, 13, 15, 26, 6);  x0 += k0;  x1 += k1  + 3u;
  tf_round4(x0, x1, 17, 29, 16, 24); x0 += k1;  x1 += ks2 + 4u;
  tf_round4(x0, x1, 13, 15, 26, 6);  x0 += ks2; x1 += k0  + 5u;
  return make_uint2(x0, x1);
}

// uniform [0,1): bitcast((bits>>9)|0x3f800000) - 1  (exact, matches jax)
__device__ __forceinline__ float u01_from_bits(uint32_t bits) {
  return __fsub_rn(__uint_as_float((bits >> 9) | 0x3f800000u), 1.0f);
}

// XLA ErfInv (f32, Giles). Separate mul/add (XLA does not form FMAs).
__device__ __forceinline__ float erfinv_xla(float x) {
  float w = -log1pf(-__fmul_rn(x, x));
  float p;
  if (w < 5.0f) {
    w = __fadd_rn(w, -2.5f);
    p = 2.81022636e-08f;
    p = __fadd_rn(3.43273939e-07f,  __fmul_rn(p, w));
    p = __fadd_rn(-3.5233877e-06f,  __fmul_rn(p, w));
    p = __fadd_rn(-4.39150654e-06f, __fmul_rn(p, w));
    p = __fadd_rn(0.00021858087f,   __fmul_rn(p, w));
    p = __fadd_rn(-0.00125372503f,  __fmul_rn(p, w));
    p = __fadd_rn(-0.00417768164f,  __fmul_rn(p, w));
    p = __fadd_rn(0.246640727f,     __fmul_rn(p, w));
    p = __fadd_rn(1.50140941f,      __fmul_rn(p, w));
  } else {
    w = __fadd_rn(__fsqrt_rn(w), -3.0f);
    p = -0.000200214257f;
    p = __fadd_rn(0.000100950558f,  __fmul_rn(p, w));
    p = __fadd_rn(0.00134934322f,   __fmul_rn(p, w));
    p = __fadd_rn(-0.00367342844f,  __fmul_rn(p, w));
    p = __fadd_rn(0.00573950773f,   __fmul_rn(p, w));
    p = __fadd_rn(-0.0076224613f,   __fmul_rn(p, w));
    p = __fadd_rn(0.00943887047f,   __fmul_rn(p, w));
    p = __fadd_rn(1.00167406f,      __fmul_rn(p, w));
    p = __fadd_rn(2.83297682f,      __fmul_rn(p, w));
  }
  return __fmul_rn(p, x);
}

// ---------------------------------------------------------------------------
// K0: per-step keys.
// ---------------------------------------------------------------------------
__global__ void __launch_bounds__(256) k_keys() {
  int t = blockIdx.x * blockDim.x + threadIdx.x;
  if (t >= T_STEPS) return;
  uint2 kt = threefry2x32(0u, 0u, 0u, (uint32_t)t);
  g_kn[t] = threefry2x32(kt.x, kt.y, 0u, 0u);
  g_kb[t] = threefry2x32(kt.x, kt.y, 0u, 1u);
}

// ---------------------------------------------------------------------------
// K1: noise gen, T-MAJOR (unchanged: alu-bound at its floor).
// ---------------------------------------------------------------------------
__global__ void __launch_bounds__(256) k_noise() {
  const int IB = N_NEUR / 128;
  const unsigned b = blockIdx.x;
  const int ib = (int)(b % IB);
  const int tb = (int)(b / IB);
  const int t  = tb * 8 + (threadIdx.x >> 5);
  const int i0 = ib * 128 + (threadIdx.x & 31) * 4;

  uint2 kn = g_kn[t];                               // warp-uniform

  const float LO  = __uint_as_float(0xBF7FFFFFu);   // nextafter(-1, 0)
  const float SQ2 = __uint_as_float(0x3FB504F3u);   // float(sqrt(2))
  const float NS  = (float)(0.6 * sqrt(0.001));     // sigma * sqrt(dt)

  float tmp[4];
#pragma unroll
  for (int j = 0; j < 4; j++) {
    uint2 r = threefry2x32(kn.x, kn.y, 0u, (uint32_t)(i0 + j));
    float f = u01_from_bits(r.x ^ r.y);
    float u = __fadd_rn(__fmul_rn(f, 2.0f), LO);
    u = fmaxf(LO, u);
    tmp[j] = __fmul_rn(__fmul_rn(SQ2, erfinv_xla(u)), NS);
  }
  float4 o; o.x = tmp[0]; o.y = tmp[1]; o.z = tmp[2]; o.w = tmp[3];
  *reinterpret_cast<float4*>(g_noise + (size_t)t * N_NEUR + i0) = o;
}

// ---------------------------------------------------------------------------
// K2: fused scan+spike. Block = 384 thr = 1 compute + 11 loader warps.
// Handshake per chunk c with partner lw = 1 + (c % 11), bar.sync(lw, 64):
//   loader: fill tile -> barR -> barC -> spike from tile -> store spikes
//   compute: barR -> exact OU chain in-place in tile -> barC
// Tile [32 t][33] padded: loader load/store uses lane=i (column), spike
// phase uses lane=t (row) — both conflict-free at pitch 33.
// ---------------------------------------------------------------------------
__global__ void __launch_bounds__(384) k_scan_spike(const float* __restrict__ state,
                                                    float* __restrict__ out) {
  __shared__ float tile[NLOAD][32][33];   // slot x t x i(+pad)
  const int w    = threadIdx.x >> 5;
  const int lane = threadIdx.x & 31;
  const int i0   = blockIdx.x * 32;

  if (w == 0) {
    // ---------------- compute warp: lane = neuron ----------------
    float x = state[i0 + lane];
    const float DT_F = 0.001f;
    for (int c = 0; c < NCHUNK; c++) {
      const int lw = 1 + (c % NLOAD);
      float* col = &tile[c % NLOAD][0][lane];
      asm volatile("bar.sync %0, 64;" :: "r"(lw) : "memory");   // ready
      float n[32];
#pragma unroll
      for (int k = 0; k < 32; k++) n[k] = col[k * 33];
#pragma unroll
      for (int k = 0; k < 32; k++) {
        x = __fadd_rn(__fsub_rn(x, __fmul_rn(x, DT_F)), n[k]);
        col[k * 33] = x;
      }
      asm volatile("bar.sync %0, 64;" :: "r"(lw) : "memory");   // x ready
    }
  } else {
    // ---------------- loader warp w: every NLOAD-th chunk ----------------
    const int slot = w - 1;
    const float RDT = 0.003f;          // rate * dt
    for (int c = w - 1; c < NCHUNK; c += NLOAD) {
      const int t0 = c * 32;
      // fill noise tile: lane = i, loop t  (coalesced LDG.32)
      const float* src = g_noise + (size_t)t0 * N_NEUR + i0 + lane;
#pragma unroll
      for (int k = 0; k < 32; k++)
        tile[slot][k][lane] = __ldcs(src + (size_t)k * N_NEUR);
      asm volatile("bar.sync %0, 64;" :: "r"(w) : "memory");    // ready
      asm volatile("bar.sync %0, 64;" :: "r"(w) : "memory");    // x ready

      // spike phase: lane = t, loop neuron columns; ballot skip per column
      uint2 kb = g_kb[t0 + lane];
#pragma unroll 4
      for (int ic = 0; ic < 32; ic++) {
        float x  = tile[slot][lane][ic];
        float pr = __fadd_rn(RDT, x);
        bool dec = (pr <= 0.0f) | (pr >= 1.0f);
        unsigned ball = __ballot_sync(0xffffffffu, dec);
        float s;
        if (ball == 0xffffffffu) {
          s = (pr >= 1.0f) ? 1.0f : 0.0f;  // u in [0,1): p<=0 never, p>=1 always
        } else {
          uint2 rr = threefry2x32(kb.x, kb.y, 0u, (uint32_t)(i0 + ic));
          float u  = u01_from_bits(rr.x ^ rr.y);
          float pc = fminf(fmaxf(pr, 0.0f), 1.0f);   // jnp.clip
          s = (u < pc) ? 1.0f : 0.0f;
        }
        tile[slot][lane][ic] = s;       // overwrite x with spike
      }
      __syncwarp();

      // store spikes: lane = i, loop t  (coalesced STG.32, t-major)
      float* dst = out + (size_t)t0 * N_NEUR + i0 + lane;
#pragma unroll
      for (int k = 0; k < 32; k++)
        dst[(size_t)k * N_NEUR] = tile[slot][k][lane];
    }
  }
}

// ---------------------------------------------------------------------------
// launch
// ---------------------------------------------------------------------------
extern "C" void kernel_launch(void* const* d_in, const int* in_sizes, int n_in,
                              void* d_out, int out_size) {
  const float* state = (const float*)d_in[0];   // zeros [N]
  float* out = (float*)d_out;                   // f32 [T*N]

  k_keys      <<<T_STEPS / 256, 256>>>();
  k_noise     <<<(N_NEUR / 128) * (T_STEPS / 8), 256>>>();
  k_scan_spike<<<N_NEUR / 32, 384>>>(state, out);
}